// round 16
// baseline (speedup 1.0000x reference)
#include <cuda_runtime.h>
#include <cuda_fp16.h>
#include <math.h>
#include <stdint.h>
#include <string.h>

#define NB   4
#define NS   1024
#define NHID 4096
#define NQH  32
#define NKVH 8
#define HD   128
#define BSR  (NB*NS)
#define GK   4096
#define NQKV 6144

#define ATT_SCALE 0.08838834764831845f
#define SOFTCAP   50.0f

// Scratch (device globals)
__device__ __half g_Ah[(size_t)BSR*GK];
__device__ __half g_Al[(size_t)BSR*GK];
__device__ __half g_B2h[(size_t)GK*NQKV];
__device__ __half g_OAh[(size_t)BSR*GK];
__device__ __half g_Wh[(size_t)GK*GK];
__device__ __half g_Qh[(size_t)BSR*NQH*HD];
__device__ __half g_Ql[(size_t)BSR*NQH*HD];
__device__ __half g_Kh[(size_t)BSR*NKVH*HD];
__device__ __half g_Vh[(size_t)BSR*NKVH*HD];

// ---------------------------------------------------------------------------
__device__ __forceinline__ uint32_t smem_u32(const void* p) {
    uint32_t a;
    asm("{ .reg .u64 t; cvta.to.shared.u64 t, %1; cvt.u32.u64 %0, t; }"
        : "=r"(a) : "l"(p));
    return a;
}
__device__ __forceinline__ void cp16(uint32_t saddr, const void* g) {
    asm volatile("cp.async.cg.shared.global [%0], [%1], 16;"
                 :: "r"(saddr), "l"(g));
}
__device__ __forceinline__ void ldsm_x4(uint32_t* r, uint32_t a) {
    asm volatile("ldmatrix.sync.aligned.m8n8.x4.shared.b16 {%0,%1,%2,%3}, [%4];"
                 : "=r"(r[0]), "=r"(r[1]), "=r"(r[2]), "=r"(r[3]) : "r"(a));
}
__device__ __forceinline__ void ldsm_x4t(uint32_t* r, uint32_t a) {
    asm volatile("ldmatrix.sync.aligned.m8n8.x4.trans.shared.b16 {%0,%1,%2,%3}, [%4];"
                 : "=r"(r[0]), "=r"(r[1]), "=r"(r[2]), "=r"(r[3]) : "r"(a));
}
__device__ __forceinline__ void mma_fp16(float* c, const uint32_t* a, const uint32_t* b) {
    asm volatile(
        "mma.sync.aligned.m16n8k16.row.col.f32.f16.f16.f32 "
        "{%0,%1,%2,%3}, {%4,%5,%6,%7}, {%8,%9}, {%0,%1,%2,%3};"
        : "+f"(c[0]), "+f"(c[1]), "+f"(c[2]), "+f"(c[3])
        : "r"(a[0]), "r"(a[1]), "r"(a[2]), "r"(a[3]), "r"(b[0]), "r"(b[1]));
}
__device__ __forceinline__ __half2 split_pair_h(float x, float y, __half2* lo) {
    __half hx = __float2half_rn(x), hy = __float2half_rn(y);
    *lo = __halves2half2(__float2half_rn(x - __half2float(hx)),
                         __float2half_rn(y - __half2float(hy)));
    return __halves2half2(hx, hy);
}

// ---------------------------------------------------------------------------
// Unified prep kernel: act split | wq|wk|wv convert | wo convert.
// ---------------------------------------------------------------------------
__global__ void prep_kernel(const float* __restrict__ hs,
                            const float* __restrict__ wq,
                            const float* __restrict__ wk,
                            const float* __restrict__ wv,
                            const float* __restrict__ wo,
                            __half* __restrict__ Ah, __half* __restrict__ Al,
                            __half* __restrict__ B2h, __half* __restrict__ Wh)
{
    int blk = blockIdx.x;
    if (blk < 16384) {
        int i = blk * 256 + threadIdx.x;
        float4 v = ((const float4*)hs)[i];
        __half2 l0, l1;
        __half2 h0 = split_pair_h(v.x, v.y, &l0);
        __half2 h1 = split_pair_h(v.z, v.w, &l1);
        ((__half2*)Ah)[2*i]   = h0;
        ((__half2*)Ah)[2*i+1] = h1;
        ((__half2*)Al)[2*i]   = l0;
        ((__half2*)Al)[2*i+1] = l1;
    } else if (blk < 40960) {
        int i = (blk - 16384) * 256 + threadIdx.x;
        size_t e = (size_t)i * 4;
        int row = (int)(e / NQKV);
        int col = (int)(e % NQKV);
        const float* src;
        if (col < 4096)       src = wq + (size_t)row * 4096 + col;
        else if (col < 5120)  src = wk + (size_t)row * 1024 + (col - 4096);
        else                  src = wv + (size_t)row * 1024 + (col - 5120);
        float4 v = *(const float4*)src;
        *(__half2*)(B2h + e)     = __floats2half2_rn(v.x, v.y);
        *(__half2*)(B2h + e + 2) = __floats2half2_rn(v.z, v.w);
    } else {
        int i = (blk - 40960) * 256 + threadIdx.x;
        float4 v = ((const float4*)wo)[i];
        ((__half2*)Wh)[2*i]   = __floats2half2_rn(v.x, v.y);
        ((__half2*)Wh)[2*i+1] = __floats2half2_rn(v.z, v.w);
    }
}

// ---------------------------------------------------------------------------
// Fused QKV GEMM: 2-pass fp16, BM=128, BN=256, BK=64, 512 thr, 3-stage.
// Fused RoPE+split epilogue (Q hi/lo, K hi, V hi). (R12 verbatim)
// ---------------------------------------------------------------------------
#define QSTG  65536
#define QBOFF 32768
#define GEMM_SMEM 196608

__global__ void __launch_bounds__(512, 1) gemm_qkv_kernel(
    const __half* __restrict__ Ahi, const __half* __restrict__ Alo,
    const __half* __restrict__ Bhi,
    const float* __restrict__ cosb, const float* __restrict__ sinb,
    __half* __restrict__ Qh, __half* __restrict__ Ql,
    __half* __restrict__ Kh, __half* __restrict__ Vh)
{
    extern __shared__ char smem[];
    const uint32_t sb = smem_u32(smem);
    const int tid = threadIdx.x;
    const int lane = tid & 31, wid = tid >> 5;
    const int mw = wid >> 2, nw = wid & 3;
    const int rowBase = blockIdx.y * 128;
    const int colBase = blockIdx.x * 256;
    const int NK = GK / 64;
    const int colb = (lane & 3) * 2;

    float acc[2][8][4];
    #pragma unroll
    for (int a = 0; a < 2; a++)
        #pragma unroll
        for (int b = 0; b < 8; b++)
            #pragma unroll
            for (int c = 0; c < 4; c++) acc[a][b][c] = 0.f;

    auto load_stage = [&](int st, int kt) {
        uint32_t base = sb + st * QSTG;
        #pragma unroll
        for (int i = 0; i < 2; i++) {
            int q = i * 512 + tid;
            int r = q >> 3, c = q & 7;
            uint32_t sw = (uint32_t)(r * 128 + ((c ^ (r & 7)) * 16));
            size_t off = (size_t)(rowBase + r) * GK + kt * 64 + c * 8;
            cp16(base + sw, Ahi + off);
            cp16(base + 16384 + sw, Alo + off);
        }
        #pragma unroll
        for (int i = 0; i < 4; i++) {
            int q = i * 512 + tid;
            int r = q >> 5, c = q & 31;
            uint32_t sw = (uint32_t)(r * 512 + ((c ^ (r & 7)) * 16));
            size_t off = (size_t)(kt * 64 + r) * NQKV + colBase + c * 8;
            cp16(base + QBOFF + sw, Bhi + off);
        }
        asm volatile("cp.async.commit_group;" ::: "memory");
    };

    load_stage(0, 0);
    load_stage(1, 1);

    for (int kt = 0; kt < NK; kt++) {
        asm volatile("cp.async.wait_group 1;" ::: "memory");
        __syncthreads();

        uint32_t base = sb + (kt % 3) * QSTG;
        #pragma unroll
        for (int ks = 0; ks < 4; ks++) {
            uint32_t ah[2][4], al[2][4], bh[4][4];
            #pragma unroll
            for (int mt = 0; mt < 2; mt++) {
                int r = mw * 32 + mt * 16 + (lane & 15);
                int c = ks * 2 + (lane >> 4);
                uint32_t a = base + r * 128 + ((c ^ (r & 7)) * 16);
                ldsm_x4(ah[mt], a);
                ldsm_x4(al[mt], a + 16384);
            }
            #pragma unroll
            for (int nt2 = 0; nt2 < 4; nt2++) {
                int r = ks * 16 + (lane & 7) + ((lane >> 3) & 1) * 8;
                int c = nw * 8 + nt2 * 2 + (lane >> 4);
                uint32_t a = base + QBOFF + r * 512 + ((c ^ (r & 7)) * 16);
                ldsm_x4t(bh[nt2], a);
            }
            #pragma unroll
            for (int mt = 0; mt < 2; mt++)
                #pragma unroll
                for (int nt = 0; nt < 8; nt++)
                    mma_fp16(acc[mt][nt], ah[mt], &bh[nt >> 1][(nt & 1) * 2]);
            #pragma unroll
            for (int mt = 0; mt < 2; mt++)
                #pragma unroll
                for (int nt = 0; nt < 8; nt++)
                    mma_fp16(acc[mt][nt], al[mt], &bh[nt >> 1][(nt & 1) * 2]);
        }
        if (kt + 2 < NK)
            load_stage((kt + 2) % 3, kt + 2);
        else
            asm volatile("cp.async.commit_group;" ::: "memory");
        __syncthreads();
    }

    // ---- fused epilogue ----
    if (colBase >= 5120) {
        #pragma unroll
        for (int mt = 0; mt < 2; mt++) {
            int r0 = rowBase + mw * 32 + mt * 16 + (lane >> 2);
            #pragma unroll
            for (int nt = 0; nt < 8; nt++) {
                int c0 = (colBase - 5120) + nw * 64 + nt * 8 + colb;
                *(__half2*)&Vh[(size_t)r0 * 1024 + c0] =
                    __floats2half2_rn(acc[mt][nt][0], acc[mt][nt][1]);
                *(__half2*)&Vh[(size_t)(r0 + 8) * 1024 + c0] =
                    __floats2half2_rn(acc[mt][nt][2], acc[mt][nt][3]);
            }
        }
        return;
    }

    float* fs = (float*)smem;
    #pragma unroll
    for (int mt = 0; mt < 2; mt++) {
        int r0 = mw * 32 + mt * 16 + (lane >> 2);
        #pragma unroll
        for (int nt = 0; nt < 8; nt++) {
            int c0 = nw * 64 + nt * 8 + colb;
            *(float2*)&fs[r0 * 264 + c0] = make_float2(acc[mt][nt][0], acc[mt][nt][1]);
            *(float2*)&fs[(r0 + 8) * 264 + c0] = make_float2(acc[mt][nt][2], acc[mt][nt][3]);
        }
    }
    __syncthreads();

    const bool isQ = colBase < 4096;
    __half* Xh = isQ ? Qh : Kh;
    __half* Xl = isQ ? Ql : (__half*)nullptr;
    const int W = isQ ? 4096 : 1024;
    const int cb = isQ ? colBase : colBase - 4096;

    #pragma unroll 4
    for (int it = 0; it < 16; it++) {
        int i = it * 512 + tid;
        int r = i >> 6, rem = i & 63;
        int hh = rem >> 5, d = (rem & 31) * 2;
        int grow = rowBase + r;
        int s = grow & (NS - 1);
        float2 x1 = *(float2*)&fs[r * 264 + hh * 128 + d];
        float2 x2 = *(float2*)&fs[r * 264 + hh * 128 + d + 64];
        float2 c1 = *(const float2*)(cosb + s * HD + d);
        float2 s1 = *(const float2*)(sinb + s * HD + d);
        float2 c2 = *(const float2*)(cosb + s * HD + d + 64);
        float2 s2 = *(const float2*)(sinb + s * HD + d + 64);
        float y1x = x1.x * c1.x - x2.x * s1.x;
        float y1y = x1.y * c1.y - x2.y * s1.y;
        float y2x = x2.x * c2.x + x1.x * s2.x;
        float y2y = x2.y * c2.y + x1.y * s2.y;
        size_t ob = (size_t)grow * W + cb + hh * 128 + d;
        if (Xl) {
            __half2 lA, lB;
            __half2 hA = split_pair_h(y1x, y1y, &lA);
            __half2 hB = split_pair_h(y2x, y2y, &lB);
            *(__half2*)(Xh + ob)      = hA;
            *(__half2*)(Xh + ob + 64) = hB;
            *(__half2*)(Xl + ob)      = lA;
            *(__half2*)(Xl + ob + 64) = lB;
        } else {
            *(__half2*)(Xh + ob)      = __floats2half2_rn(y1x, y1y);
            *(__half2*)(Xh + ob + 64) = __floats2half2_rn(y2x, y2y);
        }
    }
}

// ---------------------------------------------------------------------------
// 1-pass FP16 out-proj v2: BM=128, BN=256, BK=64, 512 thr, 4-stage.
// Same mainloop family as the measured-faster QKV kernel. smem 192KB.
// ---------------------------------------------------------------------------
#define OSTG  49152
#define OBOFF 16384

__global__ void __launch_bounds__(512, 1) gemm_out_kernel(
    const __half* __restrict__ Ahi, const __half* __restrict__ Bhi,
    float* __restrict__ C, int N)
{
    extern __shared__ char smem[];
    const uint32_t sb = smem_u32(smem);
    const int tid = threadIdx.x;
    const int lane = tid & 31, wid = tid >> 5;
    const int mw = wid >> 2, nw = wid & 3;          // 4 x 4 warp grid
    const int rowBase = blockIdx.y * 128;
    const int colBase = blockIdx.x * 256;
    const int NK = GK / 64;

    float acc[2][8][4];
    #pragma unroll
    for (int a = 0; a < 2; a++)
        #pragma unroll
        for (int b = 0; b < 8; b++)
            #pragma unroll
            for (int c = 0; c < 4; c++) acc[a][b][c] = 0.f;

    auto load_stage = [&](int st, int kt) {
        uint32_t base = sb + st * OSTG;
        // A: 128 rows x 8 chunks = 1024 chunks, 2/thread
        #pragma unroll
        for (int i = 0; i < 2; i++) {
            int q = i * 512 + tid;
            int r = q >> 3, c = q & 7;
            uint32_t sw = (uint32_t)(r * 128 + ((c ^ (r & 7)) * 16));
            size_t off = (size_t)(rowBase + r) * GK + kt * 64 + c * 8;
            cp16(base + sw, Ahi + off);
        }
        // B: 64 rows x 32 chunks = 2048 chunks, 4/thread (pitch 512B)
        #pragma unroll
        for (int i = 0; i < 4; i++) {
            int q = i * 512 + tid;
            int r = q >> 5, c = q & 31;
            uint32_t sw = (uint32_t)(r * 512 + ((c ^ (r & 7)) * 16));
            size_t off = (size_t)(kt * 64 + r) * N + colBase + c * 8;
            cp16(base + OBOFF + sw, Bhi + off);
        }
        asm volatile("cp.async.commit_group;" ::: "memory");
    };

    load_stage(0, 0);
    load_stage(1, 1);
    load_stage(2, 2);

    for (int kt = 0; kt < NK; kt++) {
        asm volatile("cp.async.wait_group 2;" ::: "memory");
        __syncthreads();

        uint32_t base = sb + (kt & 3) * OSTG;
        #pragma unroll
        for (int ks = 0; ks < 4; ks++) {
            uint32_t ah[2][4], bh[4][4];
            #pragma unroll
            for (int mt = 0; mt < 2; mt++) {
                int r = mw * 32 + mt * 16 + (lane & 15);
                int c = ks * 2 + (lane >> 4);
                ldsm_x4(ah[mt], base + r * 128 + ((c ^ (r & 7)) * 16));
            }
            #pragma unroll
            for (int nt2 = 0; nt2 < 4; nt2++) {
                int r = ks * 16 + (lane & 7) + ((lane >> 3) & 1) * 8;
                int c = nw * 8 + nt2 * 2 + (lane >> 4);
                ldsm_x4t(bh[nt2], base + OBOFF + r * 512 + ((c ^ (r & 7)) * 16));
            }
            #pragma unroll
            for (int mt = 0; mt < 2; mt++)
                #pragma unroll
                for (int nt = 0; nt < 8; nt++)
                    mma_fp16(acc[mt][nt], ah[mt], &bh[nt >> 1][(nt & 1) * 2]);
        }
        if (kt + 3 < NK)
            load_stage((kt + 3) & 3, kt + 3);
        else
            asm volatile("cp.async.commit_group;" ::: "memory");
        __syncthreads();
    }

    #pragma unroll
    for (int mt = 0; mt < 2; mt++) {
        int r0 = rowBase + mw * 32 + mt * 16 + (lane >> 2);
        #pragma unroll
        for (int nt = 0; nt < 8; nt++) {
            int c0 = colBase + nw * 64 + nt * 8 + (lane & 3) * 2;
            *(float2*)&C[(size_t)r0 * N + c0] = make_float2(acc[mt][nt][0], acc[mt][nt][1]);
            *(float2*)&C[(size_t)(r0 + 8) * N + c0] = make_float2(acc[mt][nt][2], acc[mt][nt][3]);
        }
    }
}

// ---------------------------------------------------------------------------
// Flash attention v6 (R12 verbatim): 128-row KV tiles, QK 2-pass fp16,
// PV 1-pass fp16, online max. smem 192KB, big-tiles-first.
// ---------------------------------------------------------------------------
#define FLASH_SMEM 196608

__global__ void __launch_bounds__(256, 1) flash_kernel(
    const __half* __restrict__ Qhi, const __half* __restrict__ Qlo,
    const __half* __restrict__ Khi, const __half* __restrict__ Vhi,
    __half* __restrict__ Ohi)
{
    extern __shared__ char smem[];
    const uint32_t sb = smem_u32(smem);
    const int qt = gridDim.x - 1 - blockIdx.x;
    const int h = blockIdx.y, b = blockIdx.z;
    const int kvh = h >> 2;
    const int tid = threadIdx.x, lane = tid & 31, w = tid >> 5;
    const int qbase = qt * 128;
    const int T = qt + 1;

    const uint32_t QHo = sb, QLo = sb + 32768;
    const uint32_t KBUF = sb + 65536;
    const uint32_t VBUF = sb + 131072;

    for (int i = tid; i < 2048; i += 256) {
        int r = i >> 4, c = i & 15;
        uint32_t sw = r * 256 + ((c ^ (r & 7)) * 16);
        size_t gq = (((size_t)b * NS + qbase + r) * NQH + h) * HD + c * 8;
        cp16(QHo + sw, Qhi + gq);
        cp16(QLo + sw, Qlo + gq);
        size_t gk = (((size_t)b * NS + r) * NKVH + kvh) * HD + c * 8;
        cp16(KBUF + sw, Khi + gk);
        cp16(VBUF + sw, Vhi + gk);
    }
    asm volatile("cp.async.commit_group;" ::: "memory");
    asm volatile("cp.async.wait_group 0;" ::: "memory");
    __syncthreads();

    float o[16][4];
    #pragma unroll
    for (int i = 0; i < 16; i++)
        #pragma unroll
        for (int j = 0; j < 4; j++) o[i][j] = 0.f;
    float m0 = -1e30f, m1 = -1e30f, l0 = 0.f, l1 = 0.f;

    const int row0 = w * 16 + (lane >> 2);
    const int colb = (lane & 3) * 2;
    const float ik = ATT_SCALE / SOFTCAP;

    for (int kt = 0; kt < T; kt++) {
        const int cur = kt & 1;
        const uint32_t KB = KBUF + cur * 32768;
        const uint32_t VB = VBUF + cur * 32768;
        const bool diag = (kt == qt);

        #pragma unroll
        for (int half = 0; half < 2; half++) {
            float s[8][4];
            #pragma unroll
            for (int i = 0; i < 8; i++)
                #pragma unroll
                for (int j = 0; j < 4; j++) s[i][j] = 0.f;

            #pragma unroll
            for (int ks = 0; ks < 8; ks++) {
                uint32_t ah[4], al[4], bh[4][4];
                {
                    int r = w * 16 + (lane & 15);
                    int c = ks * 2 + (lane >> 4);
                    uint32_t ad = QHo + r * 256 + ((c ^ (r & 7)) * 16);
                    ldsm_x4(ah, ad);
                    ldsm_x4(al, ad + 32768);
                }
                #pragma unroll
                for (int p = 0; p < 4; p++) {
                    int n = half * 64 + p * 16 + (lane & 15);
                    int c = ks * 2 + (lane >> 4);
                    ldsm_x4(bh[p], KB + n * 256 + ((c ^ (n & 7)) * 16));
                }
                #pragma unroll
                for (int p = 0; p < 4; p++) {
                    uint32_t b0[2] = {bh[p][0], bh[p][2]}, b1[2] = {bh[p][1], bh[p][3]};
                    mma_fp16(s[2*p],   ah, b0);
                    mma_fp16(s[2*p+1], ah, b1);
                }
                #pragma unroll
                for (int p = 0; p < 4; p++) {
                    uint32_t b0[2] = {bh[p][0], bh[p][2]}, b1[2] = {bh[p][1], bh[p][3]};
                    mma_fp16(s[2*p],   al, b0);
                    mma_fp16(s[2*p+1], al, b1);
                }
            }

            if (half == 0 && kt + 1 < T) {
                int kb = (kt + 1) * 128;
                uint32_t KN = KBUF + (cur ^ 1) * 32768;
                uint32_t VN = VBUF + (cur ^ 1) * 32768;
                for (int i = tid; i < 2048; i += 256) {
                    int r = i >> 4, c = i & 15;
                    uint32_t sw = r * 256 + ((c ^ (r & 7)) * 16);
                    size_t g = (((size_t)b * NS + kb + r) * NKVH + kvh) * HD + c * 8;
                    cp16(KN + sw, Khi + g);
                    cp16(VN + sw, Vhi + g);
                }
                asm volatile("cp.async.commit_group;" ::: "memory");
            }

            float mx0 = -1e30f, mx1 = -1e30f;
            #pragma unroll
            for (int nt = 0; nt < 8; nt++) {
                #pragma unroll
                for (int e = 0; e < 4; e++) {
                    int col = kt * 128 + half * 64 + nt * 8 + colb + (e & 1);
                    int row = qbase + row0 + (e >> 1) * 8;
                    float x = s[nt][e] * ik;
                    float x2 = x * x;
                    float t = x * (1.f + x2 * (-0.333333343f +
                              x2 * (0.133333333f + x2 * (-0.0539682540f))));
                    float sc = SOFTCAP * t;
                    if (diag && col > row) sc = -1e30f;
                    s[nt][e] = sc;
                    if (e < 2) mx0 = fmaxf(mx0, sc);
                    else       mx1 = fmaxf(mx1, sc);
                }
            }
            mx0 = fmaxf(mx0, __shfl_xor_sync(0xffffffffu, mx0, 1));
            mx0 = fmaxf(mx0, __shfl_xor_sync(0xffffffffu, mx0, 2));
            mx1 = fmaxf(mx1, __shfl_xor_sync(0xffffffffu, mx1, 1));
            mx1 = fmaxf(mx1, __shfl_xor_sync(0xffffffffu, mx1, 2));
            float mn0 = fmaxf(m0, mx0), mn1 = fmaxf(m1, mx1);
            float a0 = __expf(m0 - mn0), a1 = __expf(m1 - mn1);
            m0 = mn0; m1 = mn1;
            l0 *= a0; l1 *= a1;

            uint32_t ph[8][2];
            #pragma unroll
            for (int nt = 0; nt < 8; nt++) {
                float p0 = __expf(s[nt][0] - mn0);
                float p1 = __expf(s[nt][1] - mn0);
                float p2 = __expf(s[nt][2] - mn1);
                float p3 = __expf(s[nt][3] - mn1);
                l0 += p0 + p1;
                l1 += p2 + p3;
                __half2 h0 = __floats2half2_rn(p0, p1);
                __half2 h1 = __floats2half2_rn(p2, p3);
                memcpy(&ph[nt][0], &h0, 4);
                memcpy(&ph[nt][1], &h1, 4);
            }
            #pragma unroll
            for (int nt = 0; nt < 16; nt++) {
                o[nt][0] *= a0; o[nt][1] *= a0;
                o[nt][2] *= a1; o[nt][3] *= a1;
            }

            #pragma unroll
            for (int ks = 0; ks < 4; ks++) {
                uint32_t pah[4] = {ph[2*ks][0], ph[2*ks][1], ph[2*ks+1][0], ph[2*ks+1][1]};
                int rv = half * 64 + ks * 16 + (lane & 7) + ((lane >> 3) & 1) * 8;
                #pragma unroll
                for (int dg = 0; dg < 8; dg++) {
                    int c = dg * 2 + (lane >> 4);
                    uint32_t vh[4];
                    ldsm_x4t(vh, VB + rv * 256 + ((c ^ (rv & 7)) * 16));
                    mma_fp16(o[2*dg],   pah, &vh[0]);
                    mma_fp16(o[2*dg+1], pah, &vh[2]);
                }
            }
        }

        if (kt + 1 < T)
            asm volatile("cp.async.wait_group 0;" ::: "memory");
        __syncthreads();
    }

    l0 += __shfl_xor_sync(0xffffffffu, l0, 1);
    l0 += __shfl_xor_sync(0xffffffffu, l0, 2);
    l1 += __shfl_xor_sync(0xffffffffu, l1, 1);
    l1 += __shfl_xor_sync(0xffffffffu, l1, 2);
    float i0 = 1.f / l0, i1 = 1.f / l1;

    #pragma unroll
    for (int nt = 0; nt < 16; nt++) {
        int col = h * HD + nt * 8 + colb;
        size_t b0 = (size_t)((size_t)b * NS + qbase + row0) * NHID + col;
        size_t b1 = (size_t)((size_t)b * NS + qbase + row0 + 8) * NHID + col;
        *(__half2*)(Ohi + b0) = __floats2half2_rn(o[nt][0] * i0, o[nt][1] * i0);
        *(__half2*)(Ohi + b1) = __floats2half2_rn(o[nt][2] * i1, o[nt][3] * i1);
    }
}

// ---------------------------------------------------------------------------
extern "C" void kernel_launch(void* const* d_in, const int* in_sizes, int n_in,
                              void* d_out, int out_size)
{
    const float* hs   = (const float*)d_in[0];
    const float* wq   = (const float*)d_in[1];
    const float* wk   = (const float*)d_in[2];
    const float* wv   = (const float*)d_in[3];
    const float* wo   = (const float*)d_in[4];
    const float* cosb = (const float*)d_in[5];
    const float* sinb = (const float*)d_in[6];
    // d_in[7] = page_table: paged scatter+gather is an exact identity -> unused
    float* out = (float*)d_out;

    __half *Ah, *Al, *B2h, *OAh, *Wh, *Qh, *Ql, *Kh, *Vh;
    cudaGetSymbolAddress((void**)&Ah, g_Ah);
    cudaGetSymbolAddress((void**)&Al, g_Al);
    cudaGetSymbolAddress((void**)&B2h, g_B2h);
    cudaGetSymbolAddress((void**)&OAh, g_OAh);
    cudaGetSymbolAddress((void**)&Wh, g_Wh);
    cudaGetSymbolAddress((void**)&Qh, g_Qh);
    cudaGetSymbolAddress((void**)&Ql, g_Ql);
    cudaGetSymbolAddress((void**)&Kh, g_Kh);
    cudaGetSymbolAddress((void**)&Vh, g_Vh);

    cudaFuncSetAttribute(gemm_qkv_kernel,
                         cudaFuncAttributeMaxDynamicSharedMemorySize, GEMM_SMEM);
    cudaFuncSetAttribute(gemm_out_kernel,
                         cudaFuncAttributeMaxDynamicSharedMemorySize, GEMM_SMEM);
    cudaFuncSetAttribute(flash_kernel,
                         cudaFuncAttributeMaxDynamicSharedMemorySize, FLASH_SMEM);

    // 0: unified prep (act split + weight converts)
    prep_kernel<<<57344, 256>>>(hs, wq, wk, wv, wo, Ah, Al, B2h, Wh);
    // 1: fused QKV GEMM + RoPE/split epilogue
    gemm_qkv_kernel<<<dim3(NQKV/256, BSR/128), 512, GEMM_SMEM>>>(
        Ah, Al, B2h, cosb, sinb, Qh, Ql, Kh, Vh);
    // 2: flash attention -> fp16 hi
    flash_kernel<<<dim3(NS / 128, NQH, NB), 256, FLASH_SMEM>>>(
        Qh, Ql, Kh, Vh, OAh);
    // 3: output projection (1-pass fp16, 512 thr, BN=256, 4-stage)
    gemm_out_kernel<<<dim3(NHID/256, BSR/128), 512, GEMM_SMEM>>>(
        OAh, Wh, out, NHID);
}

// round 17
// speedup vs baseline: 1.0700x; 1.0700x over previous
#include <cuda_runtime.h>
#include <cuda_fp16.h>
#include <math.h>
#include <stdint.h>
#include <string.h>

#define NB   4
#define NS   1024
#define NHID 4096
#define NQH  32
#define NKVH 8
#define HD   128
#define BSR  (NB*NS)
#define GK   4096
#define NQKV 6144

#define ATT_SCALE 0.08838834764831845f
#define SOFTCAP   50.0f

// Scratch (device globals)
__device__ __half g_Ah[(size_t)BSR*GK];
__device__ __half g_Al[(size_t)BSR*GK];
__device__ __half g_B2h[(size_t)GK*NQKV];
__device__ __half g_OAh[(size_t)BSR*GK];
__device__ __half g_Wh[(size_t)GK*GK];
__device__ __half g_Qh[(size_t)BSR*NQH*HD];
__device__ __half g_Kh[(size_t)BSR*NKVH*HD];
__device__ __half g_Vh[(size_t)BSR*NKVH*HD];

// ---------------------------------------------------------------------------
__device__ __forceinline__ uint32_t smem_u32(const void* p) {
    uint32_t a;
    asm("{ .reg .u64 t; cvta.to.shared.u64 t, %1; cvt.u32.u64 %0, t; }"
        : "=r"(a) : "l"(p));
    return a;
}
__device__ __forceinline__ void cp16(uint32_t saddr, const void* g) {
    asm volatile("cp.async.cg.shared.global [%0], [%1], 16;"
                 :: "r"(saddr), "l"(g));
}
__device__ __forceinline__ void ldsm_x4(uint32_t* r, uint32_t a) {
    asm volatile("ldmatrix.sync.aligned.m8n8.x4.shared.b16 {%0,%1,%2,%3}, [%4];"
                 : "=r"(r[0]), "=r"(r[1]), "=r"(r[2]), "=r"(r[3]) : "r"(a));
}
__device__ __forceinline__ void ldsm_x4t(uint32_t* r, uint32_t a) {
    asm volatile("ldmatrix.sync.aligned.m8n8.x4.trans.shared.b16 {%0,%1,%2,%3}, [%4];"
                 : "=r"(r[0]), "=r"(r[1]), "=r"(r[2]), "=r"(r[3]) : "r"(a));
}
__device__ __forceinline__ void mma_fp16(float* c, const uint32_t* a, const uint32_t* b) {
    asm volatile(
        "mma.sync.aligned.m16n8k16.row.col.f32.f16.f16.f32 "
        "{%0,%1,%2,%3}, {%4,%5,%6,%7}, {%8,%9}, {%0,%1,%2,%3};"
        : "+f"(c[0]), "+f"(c[1]), "+f"(c[2]), "+f"(c[3])
        : "r"(a[0]), "r"(a[1]), "r"(a[2]), "r"(a[3]), "r"(b[0]), "r"(b[1]));
}
__device__ __forceinline__ __half2 split_pair_h(float x, float y, __half2* lo) {
    __half hx = __float2half_rn(x), hy = __float2half_rn(y);
    *lo = __halves2half2(__float2half_rn(x - __half2float(hx)),
                         __float2half_rn(y - __half2float(hy)));
    return __halves2half2(hx, hy);
}

// ---------------------------------------------------------------------------
// Unified prep kernel: act split | wq|wk|wv convert | wo convert.
// ---------------------------------------------------------------------------
__global__ void prep_kernel(const float* __restrict__ hs,
                            const float* __restrict__ wq,
                            const float* __restrict__ wk,
                            const float* __restrict__ wv,
                            const float* __restrict__ wo,
                            __half* __restrict__ Ah, __half* __restrict__ Al,
                            __half* __restrict__ B2h, __half* __restrict__ Wh)
{
    int blk = blockIdx.x;
    if (blk < 16384) {
        int i = blk * 256 + threadIdx.x;
        float4 v = ((const float4*)hs)[i];
        __half2 l0, l1;
        __half2 h0 = split_pair_h(v.x, v.y, &l0);
        __half2 h1 = split_pair_h(v.z, v.w, &l1);
        ((__half2*)Ah)[2*i]   = h0;
        ((__half2*)Ah)[2*i+1] = h1;
        ((__half2*)Al)[2*i]   = l0;
        ((__half2*)Al)[2*i+1] = l1;
    } else if (blk < 40960) {
        int i = (blk - 16384) * 256 + threadIdx.x;
        size_t e = (size_t)i * 4;
        int row = (int)(e / NQKV);
        int col = (int)(e % NQKV);
        const float* src;
        if (col < 4096)       src = wq + (size_t)row * 4096 + col;
        else if (col < 5120)  src = wk + (size_t)row * 1024 + (col - 4096);
        else                  src = wv + (size_t)row * 1024 + (col - 5120);
        float4 v = *(const float4*)src;
        *(__half2*)(B2h + e)     = __floats2half2_rn(v.x, v.y);
        *(__half2*)(B2h + e + 2) = __floats2half2_rn(v.z, v.w);
    } else {
        int i = (blk - 40960) * 256 + threadIdx.x;
        float4 v = ((const float4*)wo)[i];
        ((__half2*)Wh)[2*i]   = __floats2half2_rn(v.x, v.y);
        ((__half2*)Wh)[2*i+1] = __floats2half2_rn(v.z, v.w);
    }
}

// ---------------------------------------------------------------------------
// Fused QKV GEMM: 2-pass fp16, BM=128, BN=256, BK=64, 512 thr, 3-stage.
// Fused RoPE epilogue (Q hi, K hi, V hi — all fp16, no lo outputs).
// ---------------------------------------------------------------------------
#define QSTG  65536
#define QBOFF 32768
#define GEMM_SMEM 196608

__global__ void __launch_bounds__(512, 1) gemm_qkv_kernel(
    const __half* __restrict__ Ahi, const __half* __restrict__ Alo,
    const __half* __restrict__ Bhi,
    const float* __restrict__ cosb, const float* __restrict__ sinb,
    __half* __restrict__ Qh, __half* __restrict__ Kh, __half* __restrict__ Vh)
{
    extern __shared__ char smem[];
    const uint32_t sb = smem_u32(smem);
    const int tid = threadIdx.x;
    const int lane = tid & 31, wid = tid >> 5;
    const int mw = wid >> 2, nw = wid & 3;
    const int rowBase = blockIdx.y * 128;
    const int colBase = blockIdx.x * 256;
    const int NK = GK / 64;
    const int colb = (lane & 3) * 2;

    float acc[2][8][4];
    #pragma unroll
    for (int a = 0; a < 2; a++)
        #pragma unroll
        for (int b = 0; b < 8; b++)
            #pragma unroll
            for (int c = 0; c < 4; c++) acc[a][b][c] = 0.f;

    auto load_stage = [&](int st, int kt) {
        uint32_t base = sb + st * QSTG;
        #pragma unroll
        for (int i = 0; i < 2; i++) {
            int q = i * 512 + tid;
            int r = q >> 3, c = q & 7;
            uint32_t sw = (uint32_t)(r * 128 + ((c ^ (r & 7)) * 16));
            size_t off = (size_t)(rowBase + r) * GK + kt * 64 + c * 8;
            cp16(base + sw, Ahi + off);
            cp16(base + 16384 + sw, Alo + off);
        }
        #pragma unroll
        for (int i = 0; i < 4; i++) {
            int q = i * 512 + tid;
            int r = q >> 5, c = q & 31;
            uint32_t sw = (uint32_t)(r * 512 + ((c ^ (r & 7)) * 16));
            size_t off = (size_t)(kt * 64 + r) * NQKV + colBase + c * 8;
            cp16(base + QBOFF + sw, Bhi + off);
        }
        asm volatile("cp.async.commit_group;" ::: "memory");
    };

    load_stage(0, 0);
    load_stage(1, 1);

    for (int kt = 0; kt < NK; kt++) {
        asm volatile("cp.async.wait_group 1;" ::: "memory");
        __syncthreads();

        uint32_t base = sb + (kt % 3) * QSTG;
        #pragma unroll
        for (int ks = 0; ks < 4; ks++) {
            uint32_t ah[2][4], al[2][4], bh[4][4];
            #pragma unroll
            for (int mt = 0; mt < 2; mt++) {
                int r = mw * 32 + mt * 16 + (lane & 15);
                int c = ks * 2 + (lane >> 4);
                uint32_t a = base + r * 128 + ((c ^ (r & 7)) * 16);
                ldsm_x4(ah[mt], a);
                ldsm_x4(al[mt], a + 16384);
            }
            #pragma unroll
            for (int nt2 = 0; nt2 < 4; nt2++) {
                int r = ks * 16 + (lane & 7) + ((lane >> 3) & 1) * 8;
                int c = nw * 8 + nt2 * 2 + (lane >> 4);
                uint32_t a = base + QBOFF + r * 512 + ((c ^ (r & 7)) * 16);
                ldsm_x4t(bh[nt2], a);
            }
            #pragma unroll
            for (int mt = 0; mt < 2; mt++)
                #pragma unroll
                for (int nt = 0; nt < 8; nt++)
                    mma_fp16(acc[mt][nt], ah[mt], &bh[nt >> 1][(nt & 1) * 2]);
            #pragma unroll
            for (int mt = 0; mt < 2; mt++)
                #pragma unroll
                for (int nt = 0; nt < 8; nt++)
                    mma_fp16(acc[mt][nt], al[mt], &bh[nt >> 1][(nt & 1) * 2]);
        }
        if (kt + 2 < NK)
            load_stage((kt + 2) % 3, kt + 2);
        else
            asm volatile("cp.async.commit_group;" ::: "memory");
        __syncthreads();
    }

    // ---- fused epilogue ----
    if (colBase >= 5120) {
        #pragma unroll
        for (int mt = 0; mt < 2; mt++) {
            int r0 = rowBase + mw * 32 + mt * 16 + (lane >> 2);
            #pragma unroll
            for (int nt = 0; nt < 8; nt++) {
                int c0 = (colBase - 5120) + nw * 64 + nt * 8 + colb;
                *(__half2*)&Vh[(size_t)r0 * 1024 + c0] =
                    __floats2half2_rn(acc[mt][nt][0], acc[mt][nt][1]);
                *(__half2*)&Vh[(size_t)(r0 + 8) * 1024 + c0] =
                    __floats2half2_rn(acc[mt][nt][2], acc[mt][nt][3]);
            }
        }
        return;
    }

    float* fs = (float*)smem;
    #pragma unroll
    for (int mt = 0; mt < 2; mt++) {
        int r0 = mw * 32 + mt * 16 + (lane >> 2);
        #pragma unroll
        for (int nt = 0; nt < 8; nt++) {
            int c0 = nw * 64 + nt * 8 + colb;
            *(float2*)&fs[r0 * 264 + c0] = make_float2(acc[mt][nt][0], acc[mt][nt][1]);
            *(float2*)&fs[(r0 + 8) * 264 + c0] = make_float2(acc[mt][nt][2], acc[mt][nt][3]);
        }
    }
    __syncthreads();

    const bool isQ = colBase < 4096;
    __half* Xh = isQ ? Qh : Kh;
    const int W = isQ ? 4096 : 1024;
    const int cb = isQ ? colBase : colBase - 4096;

    #pragma unroll 4
    for (int it = 0; it < 16; it++) {
        int i = it * 512 + tid;
        int r = i >> 6, rem = i & 63;
        int hh = rem >> 5, d = (rem & 31) * 2;
        int grow = rowBase + r;
        int s = grow & (NS - 1);
        float2 x1 = *(float2*)&fs[r * 264 + hh * 128 + d];
        float2 x2 = *(float2*)&fs[r * 264 + hh * 128 + d + 64];
        float2 c1 = *(const float2*)(cosb + s * HD + d);
        float2 s1 = *(const float2*)(sinb + s * HD + d);
        float2 c2 = *(const float2*)(cosb + s * HD + d + 64);
        float2 s2 = *(const float2*)(sinb + s * HD + d + 64);
        float y1x = x1.x * c1.x - x2.x * s1.x;
        float y1y = x1.y * c1.y - x2.y * s1.y;
        float y2x = x2.x * c2.x + x1.x * s2.x;
        float y2y = x2.y * c2.y + x1.y * s2.y;
        size_t ob = (size_t)grow * W + cb + hh * 128 + d;
        *(__half2*)(Xh + ob)      = __floats2half2_rn(y1x, y1y);
        *(__half2*)(Xh + ob + 64) = __floats2half2_rn(y2x, y2y);
    }
}

// ---------------------------------------------------------------------------
// 1-pass FP16 out-proj (R12 known-good): BM=128, BN=128, BK=64, 256 thr,
// 3-stage, 2 CTAs/SM. smem 96KB.
// ---------------------------------------------------------------------------
#define OSTG  32768
#define OBOFF 16384
#define OUT_SMEM 98304

__global__ void __launch_bounds__(256, 2) gemm_out_kernel(
    const __half* __restrict__ Ahi, const __half* __restrict__ Bhi,
    float* __restrict__ C, int N)
{
    extern __shared__ char smem[];
    const uint32_t sb = smem_u32(smem);
    const int tid = threadIdx.x;
    const int lane = tid & 31, wid = tid >> 5;
    const int mw = wid >> 1, nw = wid & 1;
    const int rowBase = blockIdx.y * 128;
    const int colBase = blockIdx.x * 128;
    const int NK = GK / 64;

    float acc[2][8][4];
    #pragma unroll
    for (int a = 0; a < 2; a++)
        #pragma unroll
        for (int b = 0; b < 8; b++)
            #pragma unroll
            for (int c = 0; c < 4; c++) acc[a][b][c] = 0.f;

    auto load_stage = [&](int st, int kt) {
        uint32_t base = sb + st * OSTG;
        #pragma unroll
        for (int i = 0; i < 4; i++) {
            int q = i * 256 + tid;
            int r = q >> 3, c = q & 7;
            uint32_t sw = (uint32_t)(r * 128 + ((c ^ (r & 7)) * 16));
            size_t off = (size_t)(rowBase + r) * GK + kt * 64 + c * 8;
            cp16(base + sw, Ahi + off);
        }
        #pragma unroll
        for (int i = 0; i < 4; i++) {
            int q = i * 256 + tid;
            int r = q >> 4, c = q & 15;
            uint32_t sw = (uint32_t)(r * 256 + ((c ^ (r & 7)) * 16));
            size_t off = (size_t)(kt * 64 + r) * N + colBase + c * 8;
            cp16(base + OBOFF + sw, Bhi + off);
        }
        asm volatile("cp.async.commit_group;" ::: "memory");
    };

    load_stage(0, 0);
    load_stage(1, 1);

    for (int kt = 0; kt < NK; kt++) {
        asm volatile("cp.async.wait_group 1;" ::: "memory");
        __syncthreads();

        uint32_t base = sb + (kt % 3) * OSTG;
        #pragma unroll
        for (int ks = 0; ks < 4; ks++) {
            uint32_t ah[2][4], bh[4][4];
            #pragma unroll
            for (int mt = 0; mt < 2; mt++) {
                int r = mw * 32 + mt * 16 + (lane & 15);
                int c = ks * 2 + (lane >> 4);
                ldsm_x4(ah[mt], base + r * 128 + ((c ^ (r & 7)) * 16));
            }
            #pragma unroll
            for (int nt2 = 0; nt2 < 4; nt2++) {
                int r = ks * 16 + (lane & 7) + ((lane >> 3) & 1) * 8;
                int c = nw * 8 + nt2 * 2 + (lane >> 4);
                ldsm_x4t(bh[nt2], base + OBOFF + r * 256 + ((c ^ (r & 7)) * 16));
            }
            #pragma unroll
            for (int mt = 0; mt < 2; mt++)
                #pragma unroll
                for (int nt = 0; nt < 8; nt++)
                    mma_fp16(acc[mt][nt], ah[mt], &bh[nt >> 1][(nt & 1) * 2]);
        }
        if (kt + 2 < NK)
            load_stage((kt + 2) % 3, kt + 2);
        else
            asm volatile("cp.async.commit_group;" ::: "memory");
        __syncthreads();
    }

    #pragma unroll
    for (int mt = 0; mt < 2; mt++) {
        int r0 = rowBase + mw * 32 + mt * 16 + (lane >> 2);
        #pragma unroll
        for (int nt = 0; nt < 8; nt++) {
            int c0 = colBase + nw * 64 + nt * 8 + (lane & 3) * 2;
            *(float2*)&C[(size_t)r0 * N + c0] = make_float2(acc[mt][nt][0], acc[mt][nt][1]);
            *(float2*)&C[(size_t)(r0 + 8) * N + c0] = make_float2(acc[mt][nt][2], acc[mt][nt][3]);
        }
    }
}

// ---------------------------------------------------------------------------
// Flash attention v7: 128-row KV tiles, QK 1-pass fp16 (Q hi only),
// PV 1-pass fp16, online max. smem 160KB, big-tiles-first.
// ---------------------------------------------------------------------------
#define FLASH_SMEM 163840

__global__ void __launch_bounds__(256, 1) flash_kernel(
    const __half* __restrict__ Qhi,
    const __half* __restrict__ Khi, const __half* __restrict__ Vhi,
    __half* __restrict__ Ohi)
{
    extern __shared__ char smem[];
    const uint32_t sb = smem_u32(smem);
    const int qt = gridDim.x - 1 - blockIdx.x;
    const int h = blockIdx.y, b = blockIdx.z;
    const int kvh = h >> 2;
    const int tid = threadIdx.x, lane = tid & 31, w = tid >> 5;
    const int qbase = qt * 128;
    const int T = qt + 1;

    const uint32_t QHo = sb;                 // 32KB (hi only)
    const uint32_t KBUF = sb + 32768;        // 2 x 32KB
    const uint32_t VBUF = sb + 98304;        // 2 x 32KB

    for (int i = tid; i < 2048; i += 256) {
        int r = i >> 4, c = i & 15;
        uint32_t sw = r * 256 + ((c ^ (r & 7)) * 16);
        size_t gq = (((size_t)b * NS + qbase + r) * NQH + h) * HD + c * 8;
        cp16(QHo + sw, Qhi + gq);
        size_t gk = (((size_t)b * NS + r) * NKVH + kvh) * HD + c * 8;
        cp16(KBUF + sw, Khi + gk);
        cp16(VBUF + sw, Vhi + gk);
    }
    asm volatile("cp.async.commit_group;" ::: "memory");
    asm volatile("cp.async.wait_group 0;" ::: "memory");
    __syncthreads();

    float o[16][4];
    #pragma unroll
    for (int i = 0; i < 16; i++)
        #pragma unroll
        for (int j = 0; j < 4; j++) o[i][j] = 0.f;
    float m0 = -1e30f, m1 = -1e30f, l0 = 0.f, l1 = 0.f;

    const int row0 = w * 16 + (lane >> 2);
    const int colb = (lane & 3) * 2;
    const float ik = ATT_SCALE / SOFTCAP;

    for (int kt = 0; kt < T; kt++) {
        const int cur = kt & 1;
        const uint32_t KB = KBUF + cur * 32768;
        const uint32_t VB = VBUF + cur * 32768;
        const bool diag = (kt == qt);

        #pragma unroll
        for (int half = 0; half < 2; half++) {
            float s[8][4];
            #pragma unroll
            for (int i = 0; i < 8; i++)
                #pragma unroll
                for (int j = 0; j < 4; j++) s[i][j] = 0.f;

            // ---- S = Q K^T : 1-pass fp16 (Q hi only)
            #pragma unroll
            for (int ks = 0; ks < 8; ks++) {
                uint32_t ah[4], bh[4][4];
                {
                    int r = w * 16 + (lane & 15);
                    int c = ks * 2 + (lane >> 4);
                    ldsm_x4(ah, QHo + r * 256 + ((c ^ (r & 7)) * 16));
                }
                #pragma unroll
                for (int p = 0; p < 4; p++) {
                    int n = half * 64 + p * 16 + (lane & 15);
                    int c = ks * 2 + (lane >> 4);
                    ldsm_x4(bh[p], KB + n * 256 + ((c ^ (n & 7)) * 16));
                }
                #pragma unroll
                for (int p = 0; p < 4; p++) {
                    uint32_t b0[2] = {bh[p][0], bh[p][2]}, b1[2] = {bh[p][1], bh[p][3]};
                    mma_fp16(s[2*p],   ah, b0);
                    mma_fp16(s[2*p+1], ah, b1);
                }
            }

            if (half == 0 && kt + 1 < T) {
                int kb = (kt + 1) * 128;
                uint32_t KN = KBUF + (cur ^ 1) * 32768;
                uint32_t VN = VBUF + (cur ^ 1) * 32768;
                for (int i = tid; i < 2048; i += 256) {
                    int r = i >> 4, c = i & 15;
                    uint32_t sw = r * 256 + ((c ^ (r & 7)) * 16);
                    size_t g = (((size_t)b * NS + kb + r) * NKVH + kvh) * HD + c * 8;
                    cp16(KN + sw, Khi + g);
                    cp16(VN + sw, Vhi + g);
                }
                asm volatile("cp.async.commit_group;" ::: "memory");
            }

            float mx0 = -1e30f, mx1 = -1e30f;
            #pragma unroll
            for (int nt = 0; nt < 8; nt++) {
                #pragma unroll
                for (int e = 0; e < 4; e++) {
                    int col = kt * 128 + half * 64 + nt * 8 + colb + (e & 1);
                    int row = qbase + row0 + (e >> 1) * 8;
                    float x = s[nt][e] * ik;
                    float x2 = x * x;
                    float t = x * (1.f + x2 * (-0.333333343f +
                              x2 * (0.133333333f + x2 * (-0.0539682540f))));
                    float sc = SOFTCAP * t;
                    if (diag && col > row) sc = -1e30f;
                    s[nt][e] = sc;
                    if (e < 2) mx0 = fmaxf(mx0, sc);
                    else       mx1 = fmaxf(mx1, sc);
                }
            }
            mx0 = fmaxf(mx0, __shfl_xor_sync(0xffffffffu, mx0, 1));
            mx0 = fmaxf(mx0, __shfl_xor_sync(0xffffffffu, mx0, 2));
            mx1 = fmaxf(mx1, __shfl_xor_sync(0xffffffffu, mx1, 1));
            mx1 = fmaxf(mx1, __shfl_xor_sync(0xffffffffu, mx1, 2));
            float mn0 = fmaxf(m0, mx0), mn1 = fmaxf(m1, mx1);
            float a0 = __expf(m0 - mn0), a1 = __expf(m1 - mn1);
            m0 = mn0; m1 = mn1;
            l0 *= a0; l1 *= a1;

            uint32_t ph[8][2];
            #pragma unroll
            for (int nt = 0; nt < 8; nt++) {
                float p0 = __expf(s[nt][0] - mn0);
                float p1 = __expf(s[nt][1] - mn0);
                float p2 = __expf(s[nt][2] - mn1);
                float p3 = __expf(s[nt][3] - mn1);
                l0 += p0 + p1;
                l1 += p2 + p3;
                __half2 h0 = __floats2half2_rn(p0, p1);
                __half2 h1 = __floats2half2_rn(p2, p3);
                memcpy(&ph[nt][0], &h0, 4);
                memcpy(&ph[nt][1], &h1, 4);
            }
            #pragma unroll
            for (int nt = 0; nt < 16; nt++) {
                o[nt][0] *= a0; o[nt][1] *= a0;
                o[nt][2] *= a1; o[nt][3] *= a1;
            }

            #pragma unroll
            for (int ks = 0; ks < 4; ks++) {
                uint32_t pah[4] = {ph[2*ks][0], ph[2*ks][1], ph[2*ks+1][0], ph[2*ks+1][1]};
                int rv = half * 64 + ks * 16 + (lane & 7) + ((lane >> 3) & 1) * 8;
                #pragma unroll
                for (int dg = 0; dg < 8; dg++) {
                    int c = dg * 2 + (lane >> 4);
                    uint32_t vh[4];
                    ldsm_x4t(vh, VB + rv * 256 + ((c ^ (rv & 7)) * 16));
                    mma_fp16(o[2*dg],   pah, &vh[0]);
                    mma_fp16(o[2*dg+1], pah, &vh[2]);
                }
            }
        }

        if (kt + 1 < T)
            asm volatile("cp.async.wait_group 0;" ::: "memory");
        __syncthreads();
    }

    l0 += __shfl_xor_sync(0xffffffffu, l0, 1);
    l0 += __shfl_xor_sync(0xffffffffu, l0, 2);
    l1 += __shfl_xor_sync(0xffffffffu, l1, 1);
    l1 += __shfl_xor_sync(0xffffffffu, l1, 2);
    float i0 = 1.f / l0, i1 = 1.f / l1;

    #pragma unroll
    for (int nt = 0; nt < 16; nt++) {
        int col = h * HD + nt * 8 + colb;
        size_t b0 = (size_t)((size_t)b * NS + qbase + row0) * NHID + col;
        size_t b1 = (size_t)((size_t)b * NS + qbase + row0 + 8) * NHID + col;
        *(__half2*)(Ohi + b0) = __floats2half2_rn(o[nt][0] * i0, o[nt][1] * i0);
        *(__half2*)(Ohi + b1) = __floats2half2_rn(o[nt][2] * i1, o[nt][3] * i1);
    }
}

// ---------------------------------------------------------------------------
extern "C" void kernel_launch(void* const* d_in, const int* in_sizes, int n_in,
                              void* d_out, int out_size)
{
    const float* hs   = (const float*)d_in[0];
    const float* wq   = (const float*)d_in[1];
    const float* wk   = (const float*)d_in[2];
    const float* wv   = (const float*)d_in[3];
    const float* wo   = (const float*)d_in[4];
    const float* cosb = (const float*)d_in[5];
    const float* sinb = (const float*)d_in[6];
    // d_in[7] = page_table: paged scatter+gather is an exact identity -> unused
    float* out = (float*)d_out;

    __half *Ah, *Al, *B2h, *OAh, *Wh, *Qh, *Kh, *Vh;
    cudaGetSymbolAddress((void**)&Ah, g_Ah);
    cudaGetSymbolAddress((void**)&Al, g_Al);
    cudaGetSymbolAddress((void**)&B2h, g_B2h);
    cudaGetSymbolAddress((void**)&OAh, g_OAh);
    cudaGetSymbolAddress((void**)&Wh, g_Wh);
    cudaGetSymbolAddress((void**)&Qh, g_Qh);
    cudaGetSymbolAddress((void**)&Kh, g_Kh);
    cudaGetSymbolAddress((void**)&Vh, g_Vh);

    cudaFuncSetAttribute(gemm_qkv_kernel,
                         cudaFuncAttributeMaxDynamicSharedMemorySize, GEMM_SMEM);
    cudaFuncSetAttribute(gemm_out_kernel,
                         cudaFuncAttributeMaxDynamicSharedMemorySize, OUT_SMEM);
    cudaFuncSetAttribute(flash_kernel,
                         cudaFuncAttributeMaxDynamicSharedMemorySize, FLASH_SMEM);

    // 0: unified prep (act split + weight converts)
    prep_kernel<<<57344, 256>>>(hs, wq, wk, wv, wo, Ah, Al, B2h, Wh);
    // 1: fused QKV GEMM + RoPE epilogue (Q/K/V all fp16 hi)
    gemm_qkv_kernel<<<dim3(NQKV/256, BSR/128), 512, GEMM_SMEM>>>(
        Ah, Al, B2h, cosb, sinb, Qh, Kh, Vh);
    // 2: flash attention (1-pass QK) -> fp16 hi
    flash_kernel<<<dim3(NS / 128, NQH, NB), 256, FLASH_SMEM>>>(
        Qh, Kh, Vh, OAh);
    // 3: output projection (1-pass fp16, 256 thr, 2 CTAs/SM — known-good)
    gemm_out_kernel<<<dim3(NHID/128, BSR/128), 256, OUT_SMEM>>>(
        OAh, Wh, out, NHID);
}